// round 6
// baseline (speedup 1.0000x reference)
#include <cuda_runtime.h>

// Malvar-He-Cutler demosaic, 16x1x1024x1024 f32 -> 16x3x1024x1024 f32.
// No shared memory, no barriers. Each thread computes a 4x4 pixel region,
// reading its 8x8 input window directly via __ldg float2 (L1 serves halo
// reuse). Outputs stored row-by-row to limit register live range.

#define HH 1024
#define WW 1024

template <int DI, int DJ>
__device__ __forceinline__ void compute_row(const float (&v)[8][8], int i0,
                                            float4& R4, float4& G4, float4& B4) {
    float ro[4], go[4], bo[4];
    #pragma unroll
    for (int q = 0; q < 4; q++) {
        const int jc = q + 2;
        const float c   = v[i0][jc];
        const float sh1 = v[i0][jc - 1] + v[i0][jc + 1];
        const float sh2 = v[i0][jc - 2] + v[i0][jc + 2];
        const float sv1 = v[i0 - 1][jc] + v[i0 + 1][jc];
        const float sv2 = v[i0 - 2][jc] + v[i0 + 2][jc];
        const float sdg = (v[i0 - 1][jc - 1] + v[i0 - 1][jc + 1]) +
                          (v[i0 + 1][jc - 1] + v[i0 + 1][jc + 1]);
        const int ei = (i0 ^ DI) & 1;       // i0-2 and i0 share parity
        const int ej = (q ^ DJ) & 1;
        if (ei == ej) {
            // red/blue site: needs k0 (green) + k1 (opposite channel)
            const float u  = sh2 + sv2;
            const float k0 = fmaf(0.25f, sh1 + sv1, 0.5f * c) - 0.125f * u;
            const float k1 = fmaf(0.25f, sdg, 0.75f * c) - 0.1875f * u;
            go[q] = k0;
            if (ei == 0) { ro[q] = c;  bo[q] = k1; }
            else         { ro[q] = k1; bo[q] = c;  }
        } else {
            // green site: needs k2 (horizontal) + k3 (vertical)
            const float k2 = fmaf(0.5f, sh1, 0.625f * c) +
                             fmaf(0.0625f, sv2, -0.125f * sh2) - 0.125f * sdg;
            const float k3 = fmaf(0.5f, sv1, 0.625f * c) +
                             fmaf(0.0625f, sh2, -0.125f * sv2) - 0.125f * sdg;
            go[q] = c;
            if (ei == 0) { ro[q] = k2; bo[q] = k3; }
            else         { ro[q] = k3; bo[q] = k2; }
        }
    }
    R4 = make_float4(ro[0], ro[1], ro[2], ro[3]);
    G4 = make_float4(go[0], go[1], go[2], go[3]);
    B4 = make_float4(bo[0], bo[1], bo[2], bo[3]);
}

template <int DI, int DJ>
__device__ __forceinline__ void process(const float (&v)[8][8], float* o, size_t hw) {
    #pragma unroll
    for (int a = 0; a < 4; a++) {
        float4 R4, G4, B4;
        compute_row<DI, DJ>(v, a + 2, R4, G4, B4);
        float* orow = o + (size_t)a * WW;
        __stcs((float4*)&orow[0],      R4);
        __stcs((float4*)&orow[hw],     G4);
        __stcs((float4*)&orow[2 * hw], B4);
    }
}

__global__ __launch_bounds__(128) void demosaic_kernel(
    const float* __restrict__ x,
    const int* __restrict__ bp,
    float* __restrict__ out)
{
    const int n  = blockIdx.z;
    const int gx = blockIdx.x * 128 + 4 * threadIdx.x;  // leftmost output col
    const int gy = blockIdx.y * 16  + 4 * threadIdx.y;  // top output row
    const float* __restrict__ xin = x + (size_t)n * (HH * WW);

    // ---- load 8x8 input window straight from global (L1 serves halo reuse)
    float v[8][8];
    const bool fastcol = (gx >= 2) && (gx + 10 <= WW);
    #pragma unroll
    for (int i = 0; i < 8; i++) {
        const int r = min(max(gy + i - 2, 0), HH - 1);
        const float* rowp = xin + (size_t)r * WW;
        if (fastcol) {
            float2 a  = __ldg((const float2*)(rowp + gx - 2));
            float2 b  = __ldg((const float2*)(rowp + gx));
            float2 c2 = __ldg((const float2*)(rowp + gx + 2));
            float2 d2 = __ldg((const float2*)(rowp + gx + 4));
            v[i][0] = a.x;  v[i][1] = a.y;
            v[i][2] = b.x;  v[i][3] = b.y;
            v[i][4] = c2.x; v[i][5] = c2.y;
            v[i][6] = d2.x; v[i][7] = d2.y;
        } else {
            #pragma unroll
            for (int j = 0; j < 8; j++)
                v[i][j] = __ldg(rowp + min(max(gx - 2 + j, 0), WW - 1));
        }
    }

    // bayer pattern -> parity flips (uniform across grid)
    const int p0 = bp[0], p1 = bp[1];
    const int di = (p0 == 2) || (p0 == 1 && p1 == 2);
    const int dj = (p0 == 2) || (p0 == 1 && p1 == 0);

    const size_t hw = (size_t)HH * WW;
    float* o = out + (size_t)n * 3 * hw + (size_t)gy * WW + gx;

    if (di == 0) {
        if (dj == 0) process<0, 0>(v, o, hw);
        else         process<0, 1>(v, o, hw);
    } else {
        if (dj == 0) process<1, 0>(v, o, hw);
        else         process<1, 1>(v, o, hw);
    }
}

extern "C" void kernel_launch(void* const* d_in, const int* in_sizes, int n_in,
                              void* d_out, int out_size)
{
    const float* x   = (const float*)d_in[0];
    const int*   bp  = (const int*)d_in[1];
    float*       out = (float*)d_out;

    const int n_img = in_sizes[0] / (HH * WW);   // 16

    dim3 block(32, 4, 1);                        // 128 threads -> 128x16 pixel tile
    dim3 grid(WW / 128, HH / 16, n_img);         // (8, 64, 16)
    demosaic_kernel<<<grid, block>>>(x, bp, out);
}

// round 7
// speedup vs baseline: 1.1293x; 1.1293x over previous
#include <cuda_runtime.h>

// Malvar-He-Cutler demosaic, 16x1x1024x1024 f32 -> 16x3x1024x1024 f32.
// No shared memory, no barriers. Each thread computes a 4x2 pixel region.
// Per input row: ONE coalesced LDG.128 of the thread's own 4 columns, then
// warp shuffles provide the +-2 column halo (edge lanes do scalar loads).

#define HH 1024
#define WW 1024
#define FULLMASK 0xFFFFFFFFu

template <int DI, int DJ>
__device__ __forceinline__ void compute_tile(const float (&v)[6][8],
                                             float4 (&R4)[2],
                                             float4 (&G4)[2],
                                             float4 (&B4)[2]) {
    #pragma unroll
    for (int a = 0; a < 2; a++) {
        float ro[4], go[4], bo[4];
        #pragma unroll
        for (int q = 0; q < 4; q++) {
            const int i0 = a + 2;
            const int jc = q + 2;
            const float c   = v[i0][jc];
            const float sh1 = v[i0][jc - 1] + v[i0][jc + 1];
            const float sh2 = v[i0][jc - 2] + v[i0][jc + 2];
            const float sv1 = v[i0 - 1][jc] + v[i0 + 1][jc];
            const float sv2 = v[i0 - 2][jc] + v[i0 + 2][jc];
            const float sdg = (v[i0 - 1][jc - 1] + v[i0 - 1][jc + 1]) +
                              (v[i0 + 1][jc - 1] + v[i0 + 1][jc + 1]);
            const int ei = (a ^ DI) & 1;
            const int ej = (q ^ DJ) & 1;
            if (ei == ej) {
                // red/blue site: needs k0 (green) + k1 (opposite channel)
                const float u  = sh2 + sv2;
                const float k0 = fmaf(0.25f, sh1 + sv1, 0.5f * c) - 0.125f * u;
                const float k1 = fmaf(0.25f, sdg, 0.75f * c) - 0.1875f * u;
                go[q] = k0;
                if (ei == 0) { ro[q] = c;  bo[q] = k1; }
                else         { ro[q] = k1; bo[q] = c;  }
            } else {
                // green site: needs k2 (horizontal) + k3 (vertical)
                const float k2 = fmaf(0.5f, sh1, 0.625f * c) +
                                 fmaf(0.0625f, sv2, -0.125f * sh2) - 0.125f * sdg;
                const float k3 = fmaf(0.5f, sv1, 0.625f * c) +
                                 fmaf(0.0625f, sh2, -0.125f * sv2) - 0.125f * sdg;
                go[q] = c;
                if (ei == 0) { ro[q] = k2; bo[q] = k3; }
                else         { ro[q] = k3; bo[q] = k2; }
            }
        }
        R4[a] = make_float4(ro[0], ro[1], ro[2], ro[3]);
        G4[a] = make_float4(go[0], go[1], go[2], go[3]);
        B4[a] = make_float4(bo[0], bo[1], bo[2], bo[3]);
    }
}

__global__ __launch_bounds__(256) void demosaic_kernel(
    const float* __restrict__ x,
    const int* __restrict__ bp,
    float* __restrict__ out)
{
    const int lane = threadIdx.x;                        // 0..31
    const int n  = blockIdx.z;
    const int gx = blockIdx.x * 128 + 4 * lane;          // leftmost output col
    const int gy = blockIdx.y * 16  + 2 * threadIdx.y;   // top output row
    const float* __restrict__ xin = x + (size_t)n * (HH * WW);

    // ---- load 8x6 window: own float4 + shuffle halo from neighbor lanes
    float v[6][8];
    #pragma unroll
    for (int i = 0; i < 6; i++) {
        const int r = min(max(gy + i - 2, 0), HH - 1);
        const float* rowp = xin + (size_t)r * WW;

        const float4 m = __ldg((const float4*)(rowp + gx));   // 16B aligned, coalesced
        float lz = __shfl_up_sync(FULLMASK, m.z, 1);
        float lw = __shfl_up_sync(FULLMASK, m.w, 1);
        float rx = __shfl_down_sync(FULLMASK, m.x, 1);
        float ry = __shfl_down_sync(FULLMASK, m.y, 1);
        if (lane == 0) {            // left halo outside the warp strip
            lz = __ldg(rowp + max(gx - 2, 0));
            lw = __ldg(rowp + max(gx - 1, 0));
        }
        if (lane == 31) {           // right halo outside the warp strip
            rx = __ldg(rowp + min(gx + 4, WW - 1));
            ry = __ldg(rowp + min(gx + 5, WW - 1));
        }
        v[i][0] = lz;  v[i][1] = lw;
        v[i][2] = m.x; v[i][3] = m.y;
        v[i][4] = m.z; v[i][5] = m.w;
        v[i][6] = rx;  v[i][7] = ry;
    }

    // bayer pattern -> parity flips (uniform across grid)
    const int p0 = bp[0], p1 = bp[1];
    const int di = (p0 == 2) || (p0 == 1 && p1 == 2);
    const int dj = (p0 == 2) || (p0 == 1 && p1 == 0);

    float4 R4[2], G4[2], B4[2];
    if (di == 0) {
        if (dj == 0) compute_tile<0, 0>(v, R4, G4, B4);
        else         compute_tile<0, 1>(v, R4, G4, B4);
    } else {
        if (dj == 0) compute_tile<1, 0>(v, R4, G4, B4);
        else         compute_tile<1, 1>(v, R4, G4, B4);
    }

    // ---- streaming float4 stores: 3 channels x 2 rows
    const size_t hw = (size_t)HH * WW;
    float* o = out + (size_t)n * 3 * hw + (size_t)gy * WW + gx;

    __stcs((float4*)&o[0],           R4[0]);
    __stcs((float4*)&o[WW],          R4[1]);
    __stcs((float4*)&o[hw],          G4[0]);
    __stcs((float4*)&o[hw + WW],     G4[1]);
    __stcs((float4*)&o[2 * hw],      B4[0]);
    __stcs((float4*)&o[2 * hw + WW], B4[1]);
}

extern "C" void kernel_launch(void* const* d_in, const int* in_sizes, int n_in,
                              void* d_out, int out_size)
{
    const float* x   = (const float*)d_in[0];
    const int*   bp  = (const int*)d_in[1];
    float*       out = (float*)d_out;

    const int n_img = in_sizes[0] / (HH * WW);   // 16

    dim3 block(32, 8, 1);                        // 256 threads -> 128x16 pixel tile
    dim3 grid(WW / 128, HH / 16, n_img);         // (8, 64, 16)
    demosaic_kernel<<<grid, block>>>(x, bp, out);
}

// round 8
// speedup vs baseline: 1.2102x; 1.0716x over previous
#include <cuda_runtime.h>

// Malvar-He-Cutler demosaic, 16x1x1024x1024 f32 -> 16x3x1024x1024 f32.
// No shared memory, no barriers, no shuffles. Each thread computes a 4x2
// pixel region. Per input row: one coalesced LDG.128 for the thread's own
// 4 columns plus two independent LDG.64 for the +-2 halo. All 18 loads are
// independent -> deep MLP; L1 serves the 6x halo reuse.

#define HH 1024
#define WW 1024

template <int DI, int DJ>
__device__ __forceinline__ void compute_tile(const float (&v)[6][8],
                                             float4 (&R4)[2],
                                             float4 (&G4)[2],
                                             float4 (&B4)[2]) {
    #pragma unroll
    for (int a = 0; a < 2; a++) {
        float ro[4], go[4], bo[4];
        #pragma unroll
        for (int q = 0; q < 4; q++) {
            const int i0 = a + 2;
            const int jc = q + 2;
            const float c   = v[i0][jc];
            const float sh1 = v[i0][jc - 1] + v[i0][jc + 1];
            const float sh2 = v[i0][jc - 2] + v[i0][jc + 2];
            const float sv1 = v[i0 - 1][jc] + v[i0 + 1][jc];
            const float sv2 = v[i0 - 2][jc] + v[i0 + 2][jc];
            const float sdg = (v[i0 - 1][jc - 1] + v[i0 - 1][jc + 1]) +
                              (v[i0 + 1][jc - 1] + v[i0 + 1][jc + 1]);
            const int ei = (a ^ DI) & 1;
            const int ej = (q ^ DJ) & 1;
            if (ei == ej) {
                // red/blue site: needs k0 (green) + k1 (opposite channel)
                const float u  = sh2 + sv2;
                const float k0 = fmaf(0.25f, sh1 + sv1, 0.5f * c) - 0.125f * u;
                const float k1 = fmaf(0.25f, sdg, 0.75f * c) - 0.1875f * u;
                go[q] = k0;
                if (ei == 0) { ro[q] = c;  bo[q] = k1; }
                else         { ro[q] = k1; bo[q] = c;  }
            } else {
                // green site: needs k2 (horizontal) + k3 (vertical)
                const float k2 = fmaf(0.5f, sh1, 0.625f * c) +
                                 fmaf(0.0625f, sv2, -0.125f * sh2) - 0.125f * sdg;
                const float k3 = fmaf(0.5f, sv1, 0.625f * c) +
                                 fmaf(0.0625f, sh2, -0.125f * sv2) - 0.125f * sdg;
                go[q] = c;
                if (ei == 0) { ro[q] = k2; bo[q] = k3; }
                else         { ro[q] = k3; bo[q] = k2; }
            }
        }
        R4[a] = make_float4(ro[0], ro[1], ro[2], ro[3]);
        G4[a] = make_float4(go[0], go[1], go[2], go[3]);
        B4[a] = make_float4(bo[0], bo[1], bo[2], bo[3]);
    }
}

__global__ __launch_bounds__(256) void demosaic_kernel(
    const float* __restrict__ x,
    const int* __restrict__ bp,
    float* __restrict__ out)
{
    const int n  = blockIdx.z;
    const int gx = blockIdx.x * 128 + 4 * threadIdx.x;  // leftmost output col
    const int gy = blockIdx.y * 16  + 2 * threadIdx.y;  // top output row
    const float* __restrict__ xin = x + (size_t)n * (HH * WW);

    // ---- load 8x6 input window: LDG.128 own cols + 2x LDG.64 halo per row
    float v[6][8];
    const bool fastcol = (gx >= 2) && (gx + 10 <= WW);
    #pragma unroll
    for (int i = 0; i < 6; i++) {
        const int r = min(max(gy + i - 2, 0), HH - 1);
        const float* rowp = xin + (size_t)r * WW;
        if (fastcol) {
            const float2 a = __ldg((const float2*)(rowp + gx - 2));
            const float4 m = __ldg((const float4*)(rowp + gx));
            const float2 d = __ldg((const float2*)(rowp + gx + 4));
            v[i][0] = a.x;  v[i][1] = a.y;
            v[i][2] = m.x;  v[i][3] = m.y;
            v[i][4] = m.z;  v[i][5] = m.w;
            v[i][6] = d.x;  v[i][7] = d.y;
        } else {
            #pragma unroll
            for (int j = 0; j < 8; j++)
                v[i][j] = __ldg(rowp + min(max(gx - 2 + j, 0), WW - 1));
        }
    }

    // bayer pattern -> parity flips (uniform across grid)
    const int p0 = bp[0], p1 = bp[1];
    const int di = (p0 == 2) || (p0 == 1 && p1 == 2);
    const int dj = (p0 == 2) || (p0 == 1 && p1 == 0);

    float4 R4[2], G4[2], B4[2];
    if (di == 0) {
        if (dj == 0) compute_tile<0, 0>(v, R4, G4, B4);
        else         compute_tile<0, 1>(v, R4, G4, B4);
    } else {
        if (dj == 0) compute_tile<1, 0>(v, R4, G4, B4);
        else         compute_tile<1, 1>(v, R4, G4, B4);
    }

    // ---- streaming float4 stores: 3 channels x 2 rows
    const size_t hw = (size_t)HH * WW;
    float* o = out + (size_t)n * 3 * hw + (size_t)gy * WW + gx;

    __stcs((float4*)&o[0],           R4[0]);
    __stcs((float4*)&o[WW],          R4[1]);
    __stcs((float4*)&o[hw],          G4[0]);
    __stcs((float4*)&o[hw + WW],     G4[1]);
    __stcs((float4*)&o[2 * hw],      B4[0]);
    __stcs((float4*)&o[2 * hw + WW], B4[1]);
}

extern "C" void kernel_launch(void* const* d_in, const int* in_sizes, int n_in,
                              void* d_out, int out_size)
{
    const float* x   = (const float*)d_in[0];
    const int*   bp  = (const int*)d_in[1];
    float*       out = (float*)d_out;

    const int n_img = in_sizes[0] / (HH * WW);   // 16

    dim3 block(32, 8, 1);                        // 256 threads -> 128x16 pixel tile
    dim3 grid(WW / 128, HH / 16, n_img);         // (8, 64, 16)
    demosaic_kernel<<<grid, block>>>(x, bp, out);
}